// round 6
// baseline (speedup 1.0000x reference)
#include <cuda_runtime.h>

// img:  (1, 64, 64, 1024) float32
// rois: (1, 1024, 4) int32  -> x, y, w, h
// out:  (1, 1024, 7, 7, 1024) float32
//
// One CTA per (roi, py); 256 threads, one float4 channel lane each.
// Fully unrolled px loop; duplicate bilinear gathers skipped with predicated
// loads into FRESH registers (no dest aliasing -> no serial load chain; ptxas
// can hoist/batch all 28 LDGs for full MLP). Fallback values resolved after
// the loads with SELs (warp-uniform predicates, branch-free).

#define POOL 7
#define HW 64
#define CV 256   // float4 lanes per pixel

// Predicated vector load into a fresh register. When pred==0 the destination
// is unused garbage; callers must select it away.
__device__ __forceinline__ float4 pred_ld(const float4* __restrict__ p, int pred)
{
    float4 v;
    asm("{ .reg .pred pq;\n\t"
        "setp.ne.s32 pq, %5, 0;\n\t"
        "mov.b32 %0, 0; mov.b32 %1, 0; mov.b32 %2, 0; mov.b32 %3, 0;\n\t"
        "@pq ld.global.nc.v4.f32 {%0,%1,%2,%3}, [%4]; }"
        : "=f"(v.x), "=f"(v.y), "=f"(v.z), "=f"(v.w)
        : "l"(p), "r"(pred));
    return v;
}

__device__ __forceinline__ float4 sel4(int p, float4 a, float4 b)
{
    float4 r;
    r.x = p ? a.x : b.x;
    r.y = p ? a.y : b.y;
    r.z = p ? a.z : b.z;
    r.w = p ? a.w : b.w;
    return r;
}

__global__ __launch_bounds__(256) void roi_pool_kernel(
    const float* __restrict__ img_,
    const int* __restrict__ rois,
    float* __restrict__ out_)
{
    const float4* __restrict__ img = reinterpret_cast<const float4*>(img_);
    float4* __restrict__ out = reinterpret_cast<float4*>(out_);

    const int py  = blockIdx.x;   // 0..6
    const int roi = blockIdx.y;   // 0..1023

    const int4 r = reinterpret_cast<const int4*>(rois)[roi];
    const int rx = r.x, ry = r.y, rw = r.z, rh = r.w;

    // ---- y axis (once per block) ----
    const float sy   = (float)rh / (float)POOL;
    const float srcy = ((float)py + 0.5f) * sy - 0.5f;
    const float fy   = floorf(srcy);
    const float ty   = srcy - fy;
    const int ylo = min(max((int)fy,     0), rh - 1);
    const int yhi = min(max((int)fy + 1, 0), rh - 1);
    const int noty = (yhi != ylo);   // 0 => bottom row == top row

    const float4* __restrict__ rowT = img + (size_t)((ry + ylo) * HW) * CV;
    const float4* __restrict__ rowB = img + (size_t)((ry + yhi) * HW) * CV;

    const int c = threadIdx.x;
    float4* __restrict__ o = out + ((size_t)roi * (POOL * POOL) + (size_t)py * POOL) * CV + c;

    const float sx   = (float)rw / (float)POOL;
    const float wty  = ty;
    const float wmty = 1.0f - ty;

    int xprev = -1;
    float4 tbR = make_float4(0.f, 0.f, 0.f, 0.f);   // resolved right column (top)
    float4 bbR = tbR;                               // resolved right column (bottom)

    #pragma unroll
    for (int px = 0; px < POOL; px++) {
        const float srcx = ((float)px + 0.5f) * sx - 0.5f;
        const float fx   = floorf(srcx);
        const float tx   = srcx - fx;
        const int xlo = min(max((int)fx,     0), rw - 1);
        const int xhi = min(max((int)fx + 1, 0), rw - 1);
        const int xa = rx + xlo;
        const int xb = rx + xhi;

        const int pa = (xa != xprev);
        const int pb = (xb != xa);

        // Independent predicated loads (no inter-iteration register deps;
        // ptxas hoists these for MLP).
        const float4 At = pred_ld(rowT + (size_t)xa * CV + c, pa);
        const float4 Ab = pred_ld(rowB + (size_t)xa * CV + c, pa & noty);
        const float4 Bt = pred_ld(rowT + (size_t)xb * CV + c, pb);
        const float4 Bb = pred_ld(rowB + (size_t)xb * CV + c, pb & noty);

        // Resolution (cheap SEL chain)
        const float4 ta = sel4(pa, At, tbR);
        const float4 ba = sel4(pa, sel4(noty, Ab, At), bbR);
        const float4 tb = sel4(pb, Bt, ta);
        const float4 bb = sel4(pb, sel4(noty, Bb, Bt), ba);

        const float wtx  = tx;
        const float wmtx = 1.0f - tx;

        float4 res;
        res.x = (ta.x * wmtx + tb.x * wtx) * wmty + (ba.x * wmtx + bb.x * wtx) * wty;
        res.y = (ta.y * wmtx + tb.y * wtx) * wmty + (ba.y * wmtx + bb.y * wtx) * wty;
        res.z = (ta.z * wmtx + tb.z * wtx) * wmty + (ba.z * wmtx + bb.z * wtx) * wty;
        res.w = (ta.w * wmtx + tb.w * wtx) * wmty + (ba.w * wmtx + bb.w * wtx) * wty;

        o[px * CV] = res;

        xprev = xb;
        tbR = tb;
        bbR = bb;
    }
}

extern "C" void kernel_launch(void* const* d_in, const int* in_sizes, int n_in,
                              void* d_out, int out_size)
{
    const float* img  = (const float*)d_in[0];
    const int*   rois = (const int*)d_in[1];
    float*       out  = (float*)d_out;

    dim3 grid(POOL, 1024);
    roi_pool_kernel<<<grid, 256>>>(img, rois, out);
}

// round 7
// speedup vs baseline: 1.6350x; 1.6350x over previous
#include <cuda_runtime.h>

// img:  (1, 64, 64, 1024) float32
// rois: (1, 1024, 4) int32  -> x, y, w, h
// out:  (1, 1024, 7, 7, 1024) float32
//
// One CTA per (roi, py); 256 threads, one float4 channel lane each.
// Fully unrolled px loop, 28 fully independent __ldg gathers (no predication,
// no select chains, no inter-iteration register deps). __launch_bounds__(256,4)
// caps regs at 64 so ptxas batches loads (MLP ~8) while keeping >=50% occupancy.

#define POOL 7
#define HW 64
#define CV 256   // float4 lanes per pixel

__global__ __launch_bounds__(256, 4) void roi_pool_kernel(
    const float* __restrict__ img_,
    const int* __restrict__ rois,
    float* __restrict__ out_)
{
    const float4* __restrict__ img = reinterpret_cast<const float4*>(img_);
    float4* __restrict__ out = reinterpret_cast<float4*>(out_);

    const int py  = blockIdx.x;   // 0..6
    const int roi = blockIdx.y;   // 0..1023

    const int4 r = reinterpret_cast<const int4*>(rois)[roi];
    const int rx = r.x, ry = r.y, rw = r.z, rh = r.w;

    // ---- y axis (once per block) ----
    const float sy   = (float)rh / (float)POOL;
    const float srcy = ((float)py + 0.5f) * sy - 0.5f;
    const float fy   = floorf(srcy);
    const float ty   = srcy - fy;
    const int ylo = min(max((int)fy,     0), rh - 1);
    const int yhi = min(max((int)fy + 1, 0), rh - 1);

    const float4* __restrict__ rowT = img + (size_t)((ry + ylo) * HW) * CV;
    const float4* __restrict__ rowB = img + (size_t)((ry + yhi) * HW) * CV;

    const int c = threadIdx.x;
    float4* __restrict__ o = out + ((size_t)roi * (POOL * POOL) + (size_t)py * POOL) * CV + c;

    const float sx   = (float)rw / (float)POOL;
    const float wty  = ty;
    const float wmty = 1.0f - ty;

    // Precompute all x coords / weights (pure uniform ALU, tiny).
    int xA[POOL], xB[POOL];
    float wx[POOL];
    #pragma unroll
    for (int px = 0; px < POOL; px++) {
        const float srcx = ((float)px + 0.5f) * sx - 0.5f;
        const float fx   = floorf(srcx);
        wx[px] = srcx - fx;
        const int xlo = min(max((int)fx,     0), rw - 1);
        const int xhi = min(max((int)fx + 1, 0), rw - 1);
        xA[px] = rx + xlo;
        xB[px] = rx + xhi;
    }

    #pragma unroll
    for (int px = 0; px < POOL; px++) {
        const float4 ta = __ldg(rowT + (size_t)xA[px] * CV + c);
        const float4 tb = __ldg(rowT + (size_t)xB[px] * CV + c);
        const float4 ba = __ldg(rowB + (size_t)xA[px] * CV + c);
        const float4 bb = __ldg(rowB + (size_t)xB[px] * CV + c);

        const float wtx  = wx[px];
        const float wmtx = 1.0f - wtx;

        float4 res;
        res.x = (ta.x * wmtx + tb.x * wtx) * wmty + (ba.x * wmtx + bb.x * wtx) * wty;
        res.y = (ta.y * wmtx + tb.y * wtx) * wmty + (ba.y * wmtx + bb.y * wtx) * wty;
        res.z = (ta.z * wmtx + tb.z * wtx) * wmty + (ba.z * wmtx + bb.z * wtx) * wty;
        res.w = (ta.w * wmtx + tb.w * wtx) * wmty + (ba.w * wmtx + bb.w * wtx) * wty;

        o[px * CV] = res;
    }
}

extern "C" void kernel_launch(void* const* d_in, const int* in_sizes, int n_in,
                              void* d_out, int out_size)
{
    const float* img  = (const float*)d_in[0];
    const int*   rois = (const int*)d_in[1];
    float*       out  = (float*)d_out;

    dim3 grid(POOL, 1024);
    roi_pool_kernel<<<grid, 256>>>(img, rois, out);
}